// round 16
// baseline (speedup 1.0000x reference)
#include <cuda_runtime.h>
#include <cuda_fp16.h>
#include <cuda_bf16.h>

#define BB 16
#define KK 256
#define ZZ 128
#define HH 128
#define BK (BB*KK)

typedef unsigned int u32;

// ---------------------------------------------------------------------------
// scratch (allocation-free: __device__ globals)
// ---------------------------------------------------------------------------
__device__ float   g_m1[BK*ZZ];
__device__ __half2 g_m2h[BK*64];   // fp16 mirror of m2 for the max pass
__device__ float   g_mm[BK*ZZ];
// pre-split, pre-swizzled bf16 weight images: [128 n][128 k], 256B row stride,
// 16B chunks XOR-swizzled by row. Exact smem images (CTAs copy 16B verbatim).
__device__ __align__(16) unsigned char g_w1h[32768], g_w1l[32768];
__device__ __align__(16) unsigned char g_w2h[32768], g_w2l[32768];
__device__ __align__(16) unsigned char g_wuh[2][32768], g_wul[2][32768];

extern __shared__ __align__(16) char dynsmem_raw[];

// smem layout for GEMM kernels
#define A_HI_OFF 0
#define A_LO_OFF 32768
#define B_HI_OFF 65536
#define B_LO_OFF 81920
#define SMEM_G   98304

// ---------------------------------------------------------------------------
// helpers
// ---------------------------------------------------------------------------
__device__ __forceinline__ u32 smem_u32(const void* p) {
  u32 a;
  asm("{ .reg .u64 t; cvta.to.shared.u64 t, %1; cvt.u32.u64 %0, t; }"
      : "=r"(a) : "l"(p));
  return a;
}
// byte offset of element (row, k) in a [rows][128k] bf16 tile, 256B row
// stride, 16B chunk index XORed with (row & 7) in its low 3 bits.
__device__ __forceinline__ u32 tile_off(int row, int k) {
  const u32 chunk = (u32)k >> 3;
  const u32 sw = (chunk & 8u) | ((chunk ^ (u32)row) & 7u);
  return (u32)row * 256u + (sw << 4) + ((u32)k & 7u) * 2u;
}
__device__ __forceinline__ void split2(float2 v, __nv_bfloat162& h, __nv_bfloat162& l) {
  const __nv_bfloat16 hx = __float2bfloat16_rn(v.x);
  const __nv_bfloat16 hy = __float2bfloat16_rn(v.y);
  h = __halves2bfloat162(hx, hy);
  l = __halves2bfloat162(__float2bfloat16_rn(v.x - __bfloat162float(hx)),
                         __float2bfloat16_rn(v.y - __bfloat162float(hy)));
}

__device__ __forceinline__ void ldm_x4(u32 a, u32& r0, u32& r1, u32& r2, u32& r3) {
  asm volatile("ldmatrix.sync.aligned.m8n8.x4.shared.b16 {%0,%1,%2,%3}, [%4];"
               : "=r"(r0), "=r"(r1), "=r"(r2), "=r"(r3) : "r"(a));
}
__device__ __forceinline__ void ldm_x2(u32 a, u32& r0, u32& r1) {
  asm volatile("ldmatrix.sync.aligned.m8n8.x2.shared.b16 {%0,%1}, [%2];"
               : "=r"(r0), "=r"(r1) : "r"(a));
}
__device__ __forceinline__ void mma_bf16(float* c, u32 a0, u32 a1, u32 a2, u32 a3,
                                         u32 b0, u32 b1) {
  asm volatile("mma.sync.aligned.m16n8k16.row.col.f32.bf16.bf16.f32 "
               "{%0,%1,%2,%3}, {%4,%5,%6,%7}, {%8,%9}, {%0,%1,%2,%3};"
               : "+f"(c[0]), "+f"(c[1]), "+f"(c[2]), "+f"(c[3])
               : "r"(a0), "r"(a1), "r"(a2), "r"(a3), "r"(b0), "r"(b1));
}

// one K=128 pass: acc[2][8][4] += A(32x128 from abase, warp rows mrow..mrow+31)
//                               @ B(64x128 from bbase)^T
__device__ __forceinline__ void gemm_pass(u32 abase, u32 bbase, float acc[2][8][4],
                                          int lane, int mrow) {
  const int tl     = lane >> 3;
  const int ar_off = ((tl & 1) << 3) + (lane & 7);  // row within a 16-row tile
  const int ac     = tl >> 1;                       // chunk sub for A
  const int bn     = lane & 7;                      // B row within n-tile
  const int bc     = (lane >> 3) & 1;               // chunk sub for B
#pragma unroll
  for (int ks = 0; ks < 8; ks++) {
    u32 a[2][4];
#pragma unroll
    for (int mt = 0; mt < 2; mt++) {
      const int r = mrow + mt * 16 + ar_off;
      const u32 chunk = (u32)(ks * 2 + ac);
      const u32 sw = (chunk & 8u) | ((chunk ^ (u32)r) & 7u);
      ldm_x4(abase + (u32)r * 256u + (sw << 4), a[mt][0], a[mt][1], a[mt][2], a[mt][3]);
    }
#pragma unroll
    for (int nt = 0; nt < 8; nt++) {
      const int rn = nt * 8 + bn;
      const u32 chunk = (u32)(ks * 2 + bc);
      const u32 sw = (chunk & 8u) | ((chunk ^ (u32)rn) & 7u);
      u32 b0, b1;
      ldm_x2(bbase + (u32)rn * 256u + (sw << 4), b0, b1);
      mma_bf16(acc[0][nt], a[0][0], a[0][1], a[0][2], a[0][3], b0, b1);
      mma_bf16(acc[1][nt], a[1][0], a[1][1], a[1][2], a[1][3], b0, b1);
    }
  }
}

// stage a [128 x 128] fp32 tile (row stride 128) into hi/lo swizzled smem.
__device__ __forceinline__ void stage_act(char* hi, char* lo,
                                          const float* __restrict__ src, int tid) {
#pragma unroll 8
  for (int i = 0; i < 64; i++) {
    const int p = i * 128 + tid;            // 0..8191
    const int row = p >> 6, k = (p & 63) * 2;
    const float2 v = *(const float2*)(src + row * ZZ + k);
    __nv_bfloat162 h, l;
    split2(v, h, l);
    const u32 off = tile_off(row, k);
    *(__nv_bfloat162*)(hi + off) = h;
    *(__nv_bfloat162*)(lo + off) = l;
  }
}
// copy a 16KB weight half-image (rows are contiguous) into smem
__device__ __forceinline__ void copy_w(char* dst, const unsigned char* src, int tid) {
#pragma unroll
  for (int i = 0; i < 8; i++)
    ((uint4*)dst)[i * 128 + tid] = ((const uint4*)src)[i * 128 + tid];
}

// ---------------------------------------------------------------------------
// Pack kernel: split weights to bf16 hi/lo, write swizzled images.
// grid=128, block=256 (32768 k-pair items).
// ---------------------------------------------------------------------------
__global__ __launch_bounds__(256) void pack_kernel(
    const float* __restrict__ W1, const float* __restrict__ W2,
    const float* __restrict__ Wu) {
  const int idx = blockIdx.x * 256 + threadIdx.x;
  const float* src;
  unsigned char *ih, *il;
  int n, k, kl;
  if (idx < 8192) {
    n = idx >> 6; k = (idx & 63) * 2; kl = k;
    src = W1 + n * ZZ + k; ih = g_w1h; il = g_w1l;
  } else if (idx < 16384) {
    const int t = idx - 8192;
    n = t >> 6; k = (t & 63) * 2; kl = k;
    src = W2 + n * ZZ + k; ih = g_w2h; il = g_w2l;
  } else {
    const int t = idx - 16384;                 // 0..16383
    n = t >> 7; k = (t & 127) * 2; kl = k & 127;
    src = Wu + n * (2 * ZZ) + k;
    const int seg = k >> 7;
    ih = g_wuh[seg]; il = g_wul[seg];
  }
  const float2 v = *(const float2*)src;
  __nv_bfloat162 h, l;
  split2(v, h, l);
  const u32 off = tile_off(n, kl);
  *(__nv_bfloat162*)(ih + off) = h;
  *(__nv_bfloat162*)(il + off) = l;
}

// ---------------------------------------------------------------------------
// Kernel 1: lin GEMMs. grid=(32 Mtiles, 4 = wset*2 + colhalf), block=128.
// D[128r x 64c] = z_tile @ W^T (bf16x3 via mma.sync HMMA).
// ws0 -> g_m1 fp32; ws1 -> g_m2h fp16.
// ---------------------------------------------------------------------------
__global__ __launch_bounds__(128) void lin_mma_kernel(
    const float* __restrict__ z,
    const float* __restrict__ b1, const float* __restrict__ b2) {
  __shared__ float s_bias[64];
  const int tid  = threadIdx.x;
  const int warp = tid >> 5;
  const int lane = tid & 31;
  const int row0 = blockIdx.x * 128;
  const int ws   = blockIdx.y >> 1;
  const int ch   = blockIdx.y & 1;

  if (tid < 64) s_bias[tid] = (ws ? b2 : b1)[ch * 64 + tid];
  copy_w(dynsmem_raw + B_HI_OFF, (ws ? g_w2h : g_w1h) + ch * 16384, tid);
  copy_w(dynsmem_raw + B_LO_OFF, (ws ? g_w2l : g_w1l) + ch * 16384, tid);
  stage_act(dynsmem_raw + A_HI_OFF, dynsmem_raw + A_LO_OFF,
            z + (size_t)row0 * ZZ, tid);
  __syncthreads();

  float acc[2][8][4];
#pragma unroll
  for (int mt = 0; mt < 2; mt++)
#pragma unroll
    for (int nt = 0; nt < 8; nt++)
#pragma unroll
      for (int i = 0; i < 4; i++) acc[mt][nt][i] = 0.0f;

  const u32 ab = smem_u32(dynsmem_raw);
  const int mrow = warp * 32;
  gemm_pass(ab + A_HI_OFF, ab + B_HI_OFF, acc, lane, mrow);
  gemm_pass(ab + A_HI_OFF, ab + B_LO_OFF, acc, lane, mrow);
  gemm_pass(ab + A_LO_OFF, ab + B_HI_OFF, acc, lane, mrow);

  const int colb = (lane & 3) * 2;
#pragma unroll
  for (int mt = 0; mt < 2; mt++) {
    const int r0 = row0 + mrow + mt * 16 + (lane >> 2);
#pragma unroll
    for (int nt = 0; nt < 8; nt++) {
      const float* c = acc[mt][nt];
      const int cl = nt * 8 + colb;          // 0..63 within half
      const int col = ch * 64 + cl;
      const float bx = s_bias[cl], by = s_bias[cl + 1];
      if (ws == 0) {
        *(float2*)(g_m1 + (size_t)r0 * ZZ + col) = make_float2(c[0] + bx, c[1] + by);
        *(float2*)(g_m1 + (size_t)(r0 + 8) * ZZ + col) = make_float2(c[2] + bx, c[3] + by);
      } else {
        g_m2h[(size_t)r0 * 64 + (col >> 1)]      = __floats2half2_rn(c[0] + bx, c[1] + by);
        g_m2h[(size_t)(r0 + 8) * 64 + (col >> 1)] = __floats2half2_rn(c[2] + bx, c[3] + by);
      }
    }
  }
}

// ---------------------------------------------------------------------------
// Kernel 2: masked neighbor max (fp16) + relu(m1 + max) -> g_mm (fp32)
// grid = (K/16, B), block = 512 (warp = one destination node i). UNCHANGED.
// ---------------------------------------------------------------------------
__global__ __launch_bounds__(512) void maxagg_kernel(const int* __restrict__ P) {
  __shared__ unsigned char s_adj[KK * 16];  // 4KB

  uint2* sh = (uint2*)dynsmem_raw;          // [256 rows][32 lanes] uint2
  const int b   = blockIdx.y;
  const int i0  = blockIdx.x * 16;
  const int tid = threadIdx.x;
  const int* Pb = P + b * KK * KK;

  {
    uint4*       d = (uint4*)sh;
    const uint4* s = (const uint4*)(g_m2h + (size_t)b * KK * 64);
#pragma unroll
    for (int c = 0; c < 8; c++) d[c * 512 + tid] = s[c * 512 + tid];
  }
#pragma unroll
  for (int c = 0; c < 8; c++) {
    const int idx = c * 512 + tid;          // 0..4095
    s_adj[idx] = (Pb[(idx >> 4) * KK + i0 + (idx & 15)] != 0);
  }
  __syncthreads();

  const int warp = tid >> 5;
  const int lane = tid & 31;
  const int i    = i0 + warp;

  unsigned words[8];
#pragma unroll
  for (int wd = 0; wd < 8; wd++) {
    const unsigned pv = s_adj[(wd * 32 + lane) * 16 + warp];
    words[wd] = __ballot_sync(0xFFFFFFFFu, pv != 0);
  }

  const __half2 ninf = __half2half2(__ushort_as_half(0xFC00));  // -inf
  __half2 a0 = ninf, a1 = ninf;
  const uint2* row = sh + lane;

#pragma unroll
  for (int wd = 0; wd < 8; wd++) {
    unsigned word = words[wd];
    const int bj = wd * 32;
    while (word) {                          // warp-uniform: only active neighbors
      const int j = bj + __ffs((int)word) - 1;
      word &= word - 1;
      const uint2 v = row[j * 32];
      a0 = __hmax2(a0, *(const __half2*)&v.x);
      a1 = __hmax2(a1, *(const __half2*)&v.y);
    }
  }

  const float2 f0 = __half22float2(a0);
  const float2 f1 = __half22float2(a1);
  const int ri = (b * KK + i) * ZZ + lane * 4;
  const float4 m1 = *(const float4*)(g_m1 + ri);
  float4 o;
  o.x = fmaxf(m1.x + f0.x, 0.0f);
  o.y = fmaxf(m1.y + f0.y, 0.0f);
  o.z = fmaxf(m1.z + f1.x, 0.0f);
  o.w = fmaxf(m1.w + f1.y, 0.0f);
  *(float4*)(g_mm + ri) = o;
}

// ---------------------------------------------------------------------------
// Kernel 3: out = relu([z, m] @ Wu^T + bu). grid=(32 Mtiles, 2 colhalf),
// block=128. K=256 as two K=128 segments accumulating in registers.
// ---------------------------------------------------------------------------
__global__ __launch_bounds__(128) void out_mma_kernel(
    const float* __restrict__ z,
    const float* __restrict__ bu, float* __restrict__ out) {
  __shared__ float s_bias[64];
  const int tid  = threadIdx.x;
  const int warp = tid >> 5;
  const int lane = tid & 31;
  const int row0 = blockIdx.x * 128;
  const int ch   = blockIdx.y;

  if (tid < 64) s_bias[tid] = bu[ch * 64 + tid];

  float acc[2][8][4];
#pragma unroll
  for (int mt = 0; mt < 2; mt++)
#pragma unroll
    for (int nt = 0; nt < 8; nt++)
#pragma unroll
      for (int i = 0; i < 4; i++) acc[mt][nt][i] = 0.0f;

  const u32 ab = smem_u32(dynsmem_raw);
  const int mrow = warp * 32;

#pragma unroll
  for (int seg = 0; seg < 2; seg++) {
    if (seg) __syncthreads();               // mma reads done before restage
    copy_w(dynsmem_raw + B_HI_OFF, g_wuh[seg] + ch * 16384, tid);
    copy_w(dynsmem_raw + B_LO_OFF, g_wul[seg] + ch * 16384, tid);
    stage_act(dynsmem_raw + A_HI_OFF, dynsmem_raw + A_LO_OFF,
              (seg ? g_mm : z) + (size_t)row0 * ZZ, tid);
    __syncthreads();
    gemm_pass(ab + A_HI_OFF, ab + B_HI_OFF, acc, lane, mrow);
    gemm_pass(ab + A_HI_OFF, ab + B_LO_OFF, acc, lane, mrow);
    gemm_pass(ab + A_LO_OFF, ab + B_HI_OFF, acc, lane, mrow);
  }

  const int colb = (lane & 3) * 2;
#pragma unroll
  for (int mt = 0; mt < 2; mt++) {
    const int r0 = row0 + mrow + mt * 16 + (lane >> 2);
#pragma unroll
    for (int nt = 0; nt < 8; nt++) {
      const float* c = acc[mt][nt];
      const int cl = nt * 8 + colb;
      const int col = ch * 64 + cl;
      const float bx = s_bias[cl], by = s_bias[cl + 1];
      *(float2*)(out + (size_t)r0 * HH + col) =
          make_float2(fmaxf(c[0] + bx, 0.0f), fmaxf(c[1] + by, 0.0f));
      *(float2*)(out + (size_t)(r0 + 8) * HH + col) =
          make_float2(fmaxf(c[2] + bx, 0.0f), fmaxf(c[3] + by, 0.0f));
    }
  }
}

// ---------------------------------------------------------------------------
extern "C" void kernel_launch(void* const* d_in, const int* in_sizes, int n_in,
                              void* d_out, int out_size) {
  const float* z  = (const float*)d_in[0];
  const int*   P  = (const int*)  d_in[1];
  const float* W1 = (const float*)d_in[2];
  const float* b1 = (const float*)d_in[3];
  const float* W2 = (const float*)d_in[4];
  const float* b2 = (const float*)d_in[5];
  const float* Wu = (const float*)d_in[6];
  const float* bu = (const float*)d_in[7];
  float* out = (float*)d_out;

  (void)cudaFuncSetAttribute(lin_mma_kernel, cudaFuncAttributeMaxDynamicSharedMemorySize, SMEM_G);
  (void)cudaFuncSetAttribute(out_mma_kernel, cudaFuncAttributeMaxDynamicSharedMemorySize, SMEM_G);
  (void)cudaFuncSetAttribute(maxagg_kernel, cudaFuncAttributeMaxDynamicSharedMemorySize, 65536);

  pack_kernel<<<128, 256>>>(W1, W2, Wu);
  lin_mma_kernel<<<dim3(32, 4), 128, SMEM_G>>>(z, b1, b2);
  maxagg_kernel<<<dim3(KK / 16, BB), 512, 65536>>>(P);
  out_mma_kernel<<<dim3(32, 2), 128, SMEM_G>>>(z, bu, out);
}